// round 1
// baseline (speedup 1.0000x reference)
#include <cuda_runtime.h>
#include <math.h>

#define CC 19
#define DD 128
#define BB 4
#define HH 512
#define WW 512
#define HWU (HH*WW)          // 262144
#define HWF (128*128)        // 16384
#define NPIX_F (BB*HWF)      // 65536
#define NPIX_U (BB*HWU)      // 1048576

// ---------------- scratch (device globals; no allocation allowed) ----------
__device__ float         g_ru_down[NPIX_F];
__device__ unsigned char g_pseudo[NPIX_F];
__device__ float         g_sum_l[CC*DD];
__device__ float         g_sum_u[CC*DD];
__device__ float         g_cnt_l[CC];
__device__ float         g_wsum_u[CC];
__device__ float         g_cnt_u[CC];
__device__ float         g_mem[CC*DD];
__device__ int           g_init[CC];
__device__ double        g_ucps;
__device__ double        g_ce[4];
__device__ double        g_cv[4];

__device__ __forceinline__ float warpSum(float v){
#pragma unroll
    for (int o = 16; o; o >>= 1) v += __shfl_down_sync(0xffffffffu, v, o);
    return v;
}

// ---------------- kernel 0: zero scratch -----------------------------------
__global__ void kZero(){
    int i = blockIdx.x * 256 + threadIdx.x;      // grid covers 65536
    if (i < NPIX_F) g_ru_down[i] = 0.f;
    if (i < CC*DD){ g_sum_l[i] = 0.f; g_sum_u[i] = 0.f; }
    if (i < CC){ g_cnt_l[i] = 0.f; g_wsum_u[i] = 0.f; g_cnt_u[i] = 0.f; }
    if (i == 0) g_ucps = 0.0;
    if (i < 4){ g_ce[i] = 0.0; g_cv[i] = 0.0; }
}

// ---------------- kernel A: per-pixel reliability + UCPS -------------------
__global__ __launch_bounds__(256) void kA(const float* __restrict__ L1,
                                          const float* __restrict__ L2){
    int idx = blockIdx.x * 256 + threadIdx.x;    // 0 .. NPIX_U-1
    int w = idx & (WW-1);
    int h = (idx >> 9) & (HH-1);
    int b = idx >> 18;
    size_t pix = (size_t)b * CC * HWU + (size_t)h * WW + w;

    float l1[CC], l2[CC], e1[CC], e2[CC];
#pragma unroll
    for (int c = 0; c < CC; c++){
        l1[c] = __ldg(&L1[pix + (size_t)c*HWU]);
        l2[c] = __ldg(&L2[pix + (size_t)c*HWU]);
    }
    float m1 = l1[0], m2 = l2[0];
    int y1 = 0, y2 = 0;
#pragma unroll
    for (int c = 1; c < CC; c++){
        if (l1[c] > m1){ m1 = l1[c]; y1 = c; }
        if (l2[c] > m2){ m2 = l2[c]; y2 = c; }
    }
    float s1 = 0.f, s2 = 0.f;
#pragma unroll
    for (int c = 0; c < CC; c++){
        e1[c] = __expf(l1[c] - m1); s1 += e1[c];
        e2[c] = __expf(l2[c] - m2); s2 += e2[c];
    }
    float lse1 = m1 + __logf(s1), lse2 = m2 + __logf(s2);
    float i1 = 1.f/s1, i2 = 1.f/s2;

    const float LOGEPS = -16.118095651f;         // log(1e-7)
    float kl = 0.f;
#pragma unroll
    for (int c = 0; c < CC; c++){
        float q1 = e1[c]*i1, q2 = e2[c]*i2;
        float logm = __logf(fmaxf(0.5f*(q1+q2), 1e-7f));
        kl += q1 * (fmaxf(l1[c]-lse1, LOGEPS) - logm)
            + q2 * (fmaxf(l2[c]-lse2, LOGEPS) - logm);
    }
    float conf = 0.5f*(i1 + i2);                 // max softmax = 1/s
    float r_u  = (y1 == y2) ? conf * __expf(-0.5f*kl) : 0.f;

    float l1y2 = 0.f, l2y1 = 0.f;
#pragma unroll
    for (int c = 0; c < CC; c++){
        if (c == y2) l1y2 = l1[c];
        if (c == y1) l2y1 = l2[c];
    }
    float contrib = r_u * ((lse1 - l1y2) + (lse2 - l2y1));

    // bilinear 4x downsample == mean of pixels (4i+1,4i+2)x(4j+1,4j+2)
    int hm = h & 3, wm = w & 3;
    int dn = (b << 14) + ((h >> 2) << 7) + (w >> 2);
    if (((hm==1)||(hm==2)) && ((wm==1)||(wm==2)))
        atomicAdd(&g_ru_down[dn], 0.25f * r_u);
    if (hm == 0 && wm == 0)
        g_pseudo[dn] = (unsigned char)((y1 == y2) ? y1 : 0);

    // block-reduce UCPS contribution
    __shared__ float sred[8];
    float v = warpSum(contrib);
    if ((threadIdx.x & 31) == 0) sred[threadIdx.x >> 5] = v;
    __syncthreads();
    if (threadIdx.x == 0){
        float t = 0.f;
#pragma unroll
        for (int k = 0; k < 8; k++) t += sred[k];
        atomicAdd(&g_ucps, (double)t);
    }
}

// ---------------- kernel B: prototypes (segment sums) ----------------------
__global__ __launch_bounds__(256) void kB(const float* __restrict__ fl1,
                                          const float* __restrict__ fl2,
                                          const float* __restrict__ fu1,
                                          const float* __restrict__ fu2,
                                          const int*   __restrict__ gt,
                                          const int*   __restrict__ cur,
                                          const int*   __restrict__ mxit){
    __shared__ float s_l[CC*133];
    __shared__ float s_u[CC*133];
    __shared__ float s_cl[CC], s_w[CC], s_cu[CC];
    __shared__ float s_tau;
    for (int i = threadIdx.x; i < CC*133; i += 256){ s_l[i] = 0.f; s_u[i] = 0.f; }
    if (threadIdx.x < CC){ s_cl[threadIdx.x]=0.f; s_w[threadIdx.x]=0.f; s_cu[threadIdx.x]=0.f; }
    if (threadIdx.x == 0){
        int mi = *mxit; if (mi < 1) mi = 1;
        double ratio = (double)(*cur) / (double)mi;
        s_tau = (float)(0.85 - 0.35 * cos(1.5707963267948966 * ratio));
    }
    __syncthreads();

    int n  = blockIdx.x * 256 + threadIdx.x;     // 0 .. NPIX_F-1
    int b  = n >> 14;
    int ij = n & (HWF-1);
    int i  = ij >> 7, j = ij & 127;

    int lab_l = gt[(size_t)b*HWU + (size_t)(i*4)*WW + (j*4)];
    int lab_u = g_pseudo[n];
    float r   = g_ru_down[n];
    float wgt = (r > s_tau) ? r : 0.f;

    atomicAdd(&s_cl[lab_l], 1.f);
    atomicAdd(&s_cu[lab_u], 1.f);
    atomicAdd(&s_w [lab_u], wgt);

    float* al = &s_l[lab_l*133];
    float* au = &s_u[lab_u*133];
    size_t base = (size_t)b * DD * HWF + ij;
#pragma unroll 4
    for (int d = 0; d < DD; d++){
        size_t o = base + (size_t)d * HWF;
        float vl = 0.5f*(__ldg(&fl1[o]) + __ldg(&fl2[o]));
        float vu = 0.5f*(__ldg(&fu1[o]) + __ldg(&fu2[o]));
        atomicAdd(&al[d], vl);
        atomicAdd(&au[d], wgt * vu);
    }
    __syncthreads();

    for (int t = threadIdx.x; t < CC*DD; t += 256){
        int c = t >> 7, d = t & 127;
        atomicAdd(&g_sum_l[t], s_l[c*133 + d]);
        atomicAdd(&g_sum_u[t], s_u[c*133 + d]);
    }
    if (threadIdx.x < CC){
        atomicAdd(&g_cnt_l [threadIdx.x], s_cl[threadIdx.x]);
        atomicAdd(&g_cnt_u [threadIdx.x], s_cu[threadIdx.x]);
        atomicAdd(&g_wsum_u[threadIdx.x], s_w [threadIdx.x]);
    }
}

// ---------------- kernel C: merge + memory update --------------------------
__global__ void kC(const float* __restrict__ memory,
                   const unsigned char* __restrict__ meminit){
    int c = blockIdx.x, d = threadIdx.x;         // 19 blocks x 128 threads
    __shared__ float swarp[4];

    float cntl = g_cnt_l[c], cntu = g_cnt_u[c], wsum = g_wsum_u[c];
    bool plp = (cntl >= 1.f), pup = (cntu >= 1.f);
    float pl = g_sum_l[c*DD + d] / (cntl + 1e-7f);
    float pu = g_sum_u[c*DD + d] / (wsum + 1e-7f);
    float merged = (plp && pup) ? (0.7f*pl + 0.3f*pu) : (plp ? pl : pu);

    float v = warpSum(merged * merged);
    if ((d & 31) == 0) swarp[d >> 5] = v;
    __syncthreads();
    float nrm = sqrtf(swarp[0] + swarp[1] + swarp[2] + swarp[3]);
    float pn = merged / fmaxf(nrm, 1e-12f);

    float mv = memory[c*DD + d];
    float ev = 0.999f*mv + 0.001f*pn;
    __syncthreads();
    float v2 = warpSum(ev * ev);
    if ((d & 31) == 0) swarp[d >> 5] = v2;
    __syncthreads();
    float n2 = sqrtf(swarp[0] + swarp[1] + swarp[2] + swarp[3]);
    float ema = ev / fmaxf(n2, 1e-12f);

    bool init = (meminit[c] != 0);
    bool present = plp || pup;
    g_mem[c*DD + d] = present ? (init ? ema : pn) : mv;
    if (d == 0) g_init[c] = (init || present) ? 1 : 0;
}

// ---------------- kernel D: hard contrastive (x4 feats via grid.y) ---------
__global__ __launch_bounds__(256) void kD(const float* __restrict__ fl1,
                                          const float* __restrict__ fl2,
                                          const float* __restrict__ fu1,
                                          const float* __restrict__ fu2,
                                          const int*   __restrict__ gt){
    int fid = blockIdx.y;
    const float* f = (fid==0) ? fl1 : (fid==1) ? fl2 : (fid==2) ? fu1 : fu2;

    __shared__ float sm[DD*20];                  // [d][c] padded to 20
    for (int t = threadIdx.x; t < DD*20; t += 256){
        int d = t / 20, c = t % 20;
        sm[t] = (c < CC) ? g_mem[c*DD + d] : 0.f;
    }
    __syncthreads();

    int n = blockIdx.x * 256 + threadIdx.x;
    int b = n >> 14;
    size_t base = (size_t)b * DD * HWF + (n & (HWF-1));

    float acc[CC];
#pragma unroll
    for (int c = 0; c < CC; c++) acc[c] = 0.f;
    float nrm = 0.f;
#pragma unroll 8
    for (int d = 0; d < DD; d++){
        float v = __ldg(&f[base + (size_t)d * HWF]);
        nrm = fmaf(v, v, nrm);
        const float* mrow = &sm[d*20];
#pragma unroll
        for (int c = 0; c < CC; c++) acc[c] = fmaf(v, mrow[c], acc[c]);
    }
    float inv = 5.0f / fmaxf(sqrtf(nrm), 1e-12f);   // 1/TAU_HARD = 5

    int lab;
    if (fid < 2){
        int j = n & 127, i = (n >> 7) & 127;
        lab = gt[(size_t)b*HWU + (size_t)(i*4)*WW + (j*4)];
    } else {
        lab = g_pseudo[n];
    }
    float valid = (float)g_init[lab];

    float mx = -1e30f;
#pragma unroll
    for (int c = 0; c < CC; c++) mx = fmaxf(mx, acc[c]);
    float s = 0.f;
#pragma unroll
    for (int c = 0; c < CC; c++) s += __expf((acc[c] - mx) * inv);
    float acclab = 0.f;
#pragma unroll
    for (int c = 0; c < CC; c++) if (c == lab) acclab = acc[c];
    float ce = mx*inv + __logf(s) - acclab*inv;

    __shared__ float sA[8], sB[8];
    float a = warpSum(ce * valid);
    float bsum = warpSum(valid);
    if ((threadIdx.x & 31) == 0){ sA[threadIdx.x >> 5] = a; sB[threadIdx.x >> 5] = bsum; }
    __syncthreads();
    if (threadIdx.x == 0){
        float ta = 0.f, tb = 0.f;
#pragma unroll
        for (int k = 0; k < 8; k++){ ta += sA[k]; tb += sB[k]; }
        atomicAdd(&g_ce[fid], (double)ta);
        atomicAdd(&g_cv[fid], (double)tb);
    }
}

// ---------------- kernel E: finalize ----------------------------------------
__global__ void kE(float* out){
    double h[4];
#pragma unroll
    for (int i = 0; i < 4; i++){
        double nv = g_cv[i];
        h[i] = (nv > 0.0) ? g_ce[i] / fmax(nv, 1.0) : 0.0;
    }
    out[0] = (float)(0.5*(h[0] + h[1]) + 0.5*(h[2] + h[3]));
    out[1] = (float)(g_ucps / (double)NPIX_U);
}

// ---------------- launcher ---------------------------------------------------
extern "C" void kernel_launch(void* const* d_in, const int* in_sizes, int n_in,
                              void* d_out, int out_size){
    const float* fl1 = (const float*)d_in[0];
    const float* fl2 = (const float*)d_in[1];
    const float* fu1 = (const float*)d_in[2];
    const float* fu2 = (const float*)d_in[3];
    // d_in[4], d_in[5] (logits_l1/l2) unused by the reference
    const float* lu1 = (const float*)d_in[6];
    const float* lu2 = (const float*)d_in[7];
    const float* mem = (const float*)d_in[8];
    const int*   gt  = (const int*)d_in[9];
    const unsigned char* meminit = (const unsigned char*)d_in[10];
    const int*   cur = (const int*)d_in[11];
    const int*   mx  = (const int*)d_in[12];

    kZero<<<256, 256>>>();
    kA<<<NPIX_U/256, 256>>>(lu1, lu2);
    kB<<<NPIX_F/256, 256>>>(fl1, fl2, fu1, fu2, gt, cur, mx);
    kC<<<CC, DD>>>(mem, meminit);
    kD<<<dim3(NPIX_F/256, 4), 256>>>(fl1, fl2, fu1, fu2, gt);
    kE<<<1, 1>>>((float*)d_out);
}

// round 2
// speedup vs baseline: 1.4127x; 1.4127x over previous
#include <cuda_runtime.h>
#include <math.h>

#define CC 19
#define DD 128
#define BB 4
#define HH 512
#define WW 512
#define HWU (HH*WW)          // 262144
#define HWF (128*128)        // 16384
#define NPIX_F (BB*HWF)      // 65536
#define NPIX_U (BB*HWU)      // 1048576

typedef unsigned long long u64;

// ---------------- scratch (device globals; no allocation allowed) ----------
__device__ float         g_ru_down[NPIX_F];
__device__ unsigned char g_pseudo[NPIX_F];
__device__ float         g_sum_l[CC*DD];
__device__ float         g_sum_u[CC*DD];
__device__ float         g_cnt_l[CC];
__device__ float         g_wsum_u[CC];
__device__ float         g_cnt_u[CC];
__device__ float         g_mem[CC*DD];
__device__ int           g_init[CC];
__device__ double        g_ucps;
__device__ double        g_ce[4];
__device__ double        g_cv[4];

__device__ __forceinline__ float warpSum(float v){
#pragma unroll
    for (int o = 16; o; o >>= 1) v += __shfl_down_sync(0xffffffffu, v, o);
    return v;
}

__device__ __forceinline__ void fma2(u64& d, u64 a, u64 b){
    asm("fma.rn.f32x2 %0, %1, %2, %0;" : "+l"(d) : "l"(a), "l"(b));
}
__device__ __forceinline__ float f2lo(u64 x){ return __uint_as_float((unsigned)(x & 0xffffffffu)); }
__device__ __forceinline__ float f2hi(u64 x){ return __uint_as_float((unsigned)(x >> 32)); }
__device__ __forceinline__ u64 fdup(float v){ unsigned u = __float_as_uint(v); return ((u64)u << 32) | u; }

// ---------------- kernels 0a/0b: zero scratch -------------------------------
__global__ void kZero1(){
    int i = blockIdx.x * 256 + threadIdx.x;
    if (i < NPIX_F) g_ru_down[i] = 0.f;
}
__global__ void kZero2(){
    int i = blockIdx.x * 256 + threadIdx.x;
    if (i < CC*DD){ g_sum_l[i] = 0.f; g_sum_u[i] = 0.f; }
    if (i < CC){ g_cnt_l[i] = 0.f; g_wsum_u[i] = 0.f; g_cnt_u[i] = 0.f; }
    if (i == 0) g_ucps = 0.0;
    if (i < 4){ g_ce[i] = 0.0; g_cv[i] = 0.0; }
}

// ---------------- kernel A: per-pixel reliability + UCPS -------------------
__global__ __launch_bounds__(256) void kA(const float* __restrict__ L1,
                                          const float* __restrict__ L2){
    int idx = blockIdx.x * 256 + threadIdx.x;    // 0 .. NPIX_U-1
    int w = idx & (WW-1);
    int h = (idx >> 9) & (HH-1);
    int b = idx >> 18;
    size_t pix = (size_t)b * CC * HWU + (size_t)h * WW + w;

    float l1[CC], l2[CC];
#pragma unroll
    for (int c = 0; c < CC; c++){
        l1[c] = __ldg(&L1[pix + (size_t)c*HWU]);
        l2[c] = __ldg(&L2[pix + (size_t)c*HWU]);
    }
    float m1 = l1[0], m2 = l2[0];
    int y1 = 0, y2 = 0;
#pragma unroll
    for (int c = 1; c < CC; c++){
        if (l1[c] > m1){ m1 = l1[c]; y1 = c; }
        if (l2[c] > m2){ m2 = l2[c]; y2 = c; }
    }
    float s1 = 0.f, s2 = 0.f;
#pragma unroll
    for (int c = 0; c < CC; c++){
        s1 += __expf(l1[c] - m1);
        s2 += __expf(l2[c] - m2);
    }
    float lse1 = m1 + __logf(s1), lse2 = m2 + __logf(s2);

    const float LOGEPS = -16.118095651f;         // log(1e-7)
    float kl = 0.f;
#pragma unroll
    for (int c = 0; c < CC; c++){
        float t1 = l1[c] - lse1, t2 = l2[c] - lse2;
        float q1 = __expf(t1),   q2 = __expf(t2);
        float logm = __logf(fmaxf(0.5f*(q1+q2), 1e-7f));
        kl += q1 * (fmaxf(t1, LOGEPS) - logm)
            + q2 * (fmaxf(t2, LOGEPS) - logm);
    }
    float conf = 0.5f*(1.f/s1 + 1.f/s2);         // max softmax = 1/s
    float r_u  = (y1 == y2) ? conf * __expf(-0.5f*kl) : 0.f;

    float l1y2 = 0.f, l2y1 = 0.f;
#pragma unroll
    for (int c = 0; c < CC; c++){
        if (c == y2) l1y2 = l1[c];
        if (c == y1) l2y1 = l2[c];
    }
    float contrib = r_u * ((lse1 - l1y2) + (lse2 - l2y1));

    // bilinear 4x downsample == mean of pixels (4i+1,4i+2)x(4j+1,4j+2)
    int hm = h & 3, wm = w & 3;
    int dn = (b << 14) + ((h >> 2) << 7) + (w >> 2);
    if (((hm==1)||(hm==2)) && ((wm==1)||(wm==2)))
        atomicAdd(&g_ru_down[dn], 0.25f * r_u);
    if (hm == 0 && wm == 0)
        g_pseudo[dn] = (unsigned char)((y1 == y2) ? y1 : 0);

    // block-reduce UCPS contribution
    __shared__ float sred[8];
    float v = warpSum(contrib);
    if ((threadIdx.x & 31) == 0) sred[threadIdx.x >> 5] = v;
    __syncthreads();
    if (threadIdx.x == 0){
        float t = 0.f;
#pragma unroll
        for (int k = 0; k < 8; k++) t += sred[k];
        atomicAdd(&g_ucps, (double)t);
    }
}

// ---------------- kernel B: prototypes (segment sums), 2 px/thread ---------
__global__ __launch_bounds__(128) void kB(const float* __restrict__ fl1,
                                          const float* __restrict__ fl2,
                                          const float* __restrict__ fu1,
                                          const float* __restrict__ fu2,
                                          const int*   __restrict__ gt,
                                          const int*   __restrict__ cur,
                                          const int*   __restrict__ mxit){
    __shared__ float s_l[CC*133];
    __shared__ float s_u[CC*133];
    __shared__ float s_cl[CC], s_w[CC], s_cu[CC];
    __shared__ float s_tau;
    for (int i = threadIdx.x; i < CC*133; i += 128){ s_l[i] = 0.f; s_u[i] = 0.f; }
    if (threadIdx.x < CC){ s_cl[threadIdx.x]=0.f; s_w[threadIdx.x]=0.f; s_cu[threadIdx.x]=0.f; }
    if (threadIdx.x == 0){
        int mi = *mxit; if (mi < 1) mi = 1;
        double ratio = (double)(*cur) / (double)mi;
        s_tau = (float)(0.85 - 0.35 * cos(1.5707963267948966 * ratio));
    }
    __syncthreads();

    int n0 = (blockIdx.x * 128 + threadIdx.x) * 2;  // even pixel of a pair
    int b  = n0 >> 14;
    int ij = n0 & (HWF-1);
    int i  = ij >> 7, j = ij & 127;

    int lab_l0 = gt[(size_t)b*HWU + (size_t)(i*4)*WW + (j*4)];
    int lab_l1 = gt[(size_t)b*HWU + (size_t)(i*4)*WW + (j*4 + 4)];
    int lab_u0 = g_pseudo[n0];
    int lab_u1 = g_pseudo[n0+1];
    float r0   = g_ru_down[n0],   r1 = g_ru_down[n0+1];
    float w0   = (r0 > s_tau) ? r0 : 0.f;
    float w1   = (r1 > s_tau) ? r1 : 0.f;
    bool  h0   = (w0 != 0.f), h1 = (w1 != 0.f);

    atomicAdd(&s_cl[lab_l0], 1.f);
    atomicAdd(&s_cl[lab_l1], 1.f);
    atomicAdd(&s_cu[lab_u0], 1.f);
    atomicAdd(&s_cu[lab_u1], 1.f);
    if (h0) atomicAdd(&s_w[lab_u0], w0);
    if (h1) atomicAdd(&s_w[lab_u1], w1);

    float* al0 = &s_l[lab_l0*133];
    float* al1 = &s_l[lab_l1*133];
    float* au0 = &s_u[lab_u0*133];
    float* au1 = &s_u[lab_u1*133];
    size_t base = (size_t)b * DD * HWF + ij;
#pragma unroll 4
    for (int d = 0; d < DD; d++){
        size_t o = base + (size_t)d * HWF;
        u64 a1 = __ldg((const u64*)&fl1[o]);
        u64 a2 = __ldg((const u64*)&fl2[o]);
        u64 b1 = __ldg((const u64*)&fu1[o]);
        u64 b2 = __ldg((const u64*)&fu2[o]);
        atomicAdd(&al0[d], 0.5f*(f2lo(a1) + f2lo(a2)));
        atomicAdd(&al1[d], 0.5f*(f2hi(a1) + f2hi(a2)));
        if (h0) atomicAdd(&au0[d], w0 * 0.5f*(f2lo(b1) + f2lo(b2)));
        if (h1) atomicAdd(&au1[d], w1 * 0.5f*(f2hi(b1) + f2hi(b2)));
    }
    __syncthreads();

    for (int t = threadIdx.x; t < CC*DD; t += 128){
        int c = t >> 7, d = t & 127;
        atomicAdd(&g_sum_l[t], s_l[c*133 + d]);
        atomicAdd(&g_sum_u[t], s_u[c*133 + d]);
    }
    if (threadIdx.x < CC){
        atomicAdd(&g_cnt_l [threadIdx.x], s_cl[threadIdx.x]);
        atomicAdd(&g_cnt_u [threadIdx.x], s_cu[threadIdx.x]);
        atomicAdd(&g_wsum_u[threadIdx.x], s_w [threadIdx.x]);
    }
}

// ---------------- kernel C: merge + memory update --------------------------
__global__ void kC(const float* __restrict__ memory,
                   const unsigned char* __restrict__ meminit){
    int c = blockIdx.x, d = threadIdx.x;         // 19 blocks x 128 threads
    __shared__ float swarp[4];

    float cntl = g_cnt_l[c], cntu = g_cnt_u[c], wsum = g_wsum_u[c];
    bool plp = (cntl >= 1.f), pup = (cntu >= 1.f);
    float pl = g_sum_l[c*DD + d] / (cntl + 1e-7f);
    float pu = g_sum_u[c*DD + d] / (wsum + 1e-7f);
    float merged = (plp && pup) ? (0.7f*pl + 0.3f*pu) : (plp ? pl : pu);

    float v = warpSum(merged * merged);
    if ((d & 31) == 0) swarp[d >> 5] = v;
    __syncthreads();
    float nrm = sqrtf(swarp[0] + swarp[1] + swarp[2] + swarp[3]);
    float pn = merged / fmaxf(nrm, 1e-12f);

    float mv = memory[c*DD + d];
    float ev = 0.999f*mv + 0.001f*pn;
    __syncthreads();
    float v2 = warpSum(ev * ev);
    if ((d & 31) == 0) swarp[d >> 5] = v2;
    __syncthreads();
    float n2 = sqrtf(swarp[0] + swarp[1] + swarp[2] + swarp[3]);
    float ema = ev / fmaxf(n2, 1e-12f);

    bool init = (meminit[c] != 0);
    bool present = plp || pup;
    g_mem[c*DD + d] = present ? (init ? ema : pn) : mv;
    if (d == 0) g_init[c] = (init || present) ? 1 : 0;
}

// ------ kernel D: hard contrastive, f32x2 packed, 2 px/thread, 4 maps ------
__global__ __launch_bounds__(256) void kD(const float* __restrict__ fl1,
                                          const float* __restrict__ fl2,
                                          const float* __restrict__ fu1,
                                          const float* __restrict__ fu2,
                                          const int*   __restrict__ gt){
    int fid = blockIdx.y;
    const float* f = (fid==0) ? fl1 : (fid==1) ? fl2 : (fid==2) ? fu1 : fu2;

    __shared__ u64 sm2[DD*20];                   // duplicated (m,m) pairs
    for (int t = threadIdx.x; t < DD*20; t += 256){
        int d = t / 20, c = t % 20;
        sm2[t] = fdup((c < CC) ? g_mem[c*DD + d] : 0.f);
    }
    __syncthreads();

    int n0 = (blockIdx.x * 256 + threadIdx.x) * 2;
    int b = n0 >> 14;
    size_t base = (size_t)b * DD * HWF + (n0 & (HWF-1));

    u64 acc[CC];
#pragma unroll
    for (int c = 0; c < CC; c++) acc[c] = 0ull;
    u64 nrm2 = 0ull;
#pragma unroll 8
    for (int d = 0; d < DD; d++){
        u64 v2 = __ldg((const u64*)&f[base + (size_t)d * HWF]);
        fma2(nrm2, v2, v2);
        const u64* row = &sm2[d*20];
#pragma unroll
        for (int c = 0; c < CC; c++) fma2(acc[c], v2, row[c]);
    }

    float blkce = 0.f, blkcv = 0.f;
#pragma unroll
    for (int half = 0; half < 2; half++){
        int n = n0 + half;
        float nrm = half ? f2hi(nrm2) : f2lo(nrm2);
        float inv = 5.0f / fmaxf(sqrtf(nrm), 1e-12f);   // 1/TAU_HARD = 5

        int lab;
        if (fid < 2){
            int j = n & 127, ii = (n >> 7) & 127;
            lab = gt[(size_t)b*HWU + (size_t)(ii*4)*WW + (j*4)];
        } else {
            lab = g_pseudo[n];
        }
        float valid = (float)g_init[lab];

        float mx = -1e30f, acclab = 0.f;
#pragma unroll
        for (int c = 0; c < CC; c++){
            float a = half ? f2hi(acc[c]) : f2lo(acc[c]);
            mx = fmaxf(mx, a);
            if (c == lab) acclab = a;
        }
        float s = 0.f;
#pragma unroll
        for (int c = 0; c < CC; c++){
            float a = half ? f2hi(acc[c]) : f2lo(acc[c]);
            s += __expf((a - mx) * inv);
        }
        float ce = mx*inv + __logf(s) - acclab*inv;
        blkce += ce * valid;
        blkcv += valid;
    }

    __shared__ float sA[8], sB[8];
    float a = warpSum(blkce);
    float bsum = warpSum(blkcv);
    if ((threadIdx.x & 31) == 0){ sA[threadIdx.x >> 5] = a; sB[threadIdx.x >> 5] = bsum; }
    __syncthreads();
    if (threadIdx.x == 0){
        float ta = 0.f, tb = 0.f;
#pragma unroll
        for (int k = 0; k < 8; k++){ ta += sA[k]; tb += sB[k]; }
        atomicAdd(&g_ce[fid], (double)ta);
        atomicAdd(&g_cv[fid], (double)tb);
    }
}

// ---------------- kernel E: finalize ----------------------------------------
__global__ void kE(float* out){
    double h[4];
#pragma unroll
    for (int i = 0; i < 4; i++){
        double nv = g_cv[i];
        h[i] = (nv > 0.0) ? g_ce[i] / fmax(nv, 1.0) : 0.0;
    }
    out[0] = (float)(0.5*(h[0] + h[1]) + 0.5*(h[2] + h[3]));
    out[1] = (float)(g_ucps / (double)NPIX_U);
}

// ---------------- launcher ---------------------------------------------------
extern "C" void kernel_launch(void* const* d_in, const int* in_sizes, int n_in,
                              void* d_out, int out_size){
    const float* fl1 = (const float*)d_in[0];
    const float* fl2 = (const float*)d_in[1];
    const float* fu1 = (const float*)d_in[2];
    const float* fu2 = (const float*)d_in[3];
    // d_in[4], d_in[5] (logits_l1/l2) unused by the reference
    const float* lu1 = (const float*)d_in[6];
    const float* lu2 = (const float*)d_in[7];
    const float* mem = (const float*)d_in[8];
    const int*   gt  = (const int*)d_in[9];
    const unsigned char* meminit = (const unsigned char*)d_in[10];
    const int*   cur = (const int*)d_in[11];
    const int*   mx  = (const int*)d_in[12];

    kZero1<<<NPIX_F/256, 256>>>();                       // idx 0
    kZero2<<<16, 256>>>();                               // idx 1
    kA<<<NPIX_U/256, 256>>>(lu1, lu2);                   // idx 2
    kB<<<NPIX_F/256, 128>>>(fl1, fl2, fu1, fu2, gt, cur, mx);  // idx 3 (capture slot)
    kC<<<CC, DD>>>(mem, meminit);                        // idx 4
    kD<<<dim3(NPIX_F/512, 4), 256>>>(fl1, fl2, fu1, fu2, gt);  // idx 5
    kE<<<1, 1>>>((float*)d_out);                         // idx 6
}

// round 3
// speedup vs baseline: 2.6254x; 1.8584x over previous
#include <cuda_runtime.h>
#include <math.h>

#define CC 19
#define DD 128
#define BB 4
#define HH 512
#define WW 512
#define HWU (HH*WW)          // 262144
#define HWF (128*128)        // 16384
#define NPIX_F (BB*HWF)      // 65536
#define NPIX_U (BB*HWU)      // 1048576
#define KD_BLOCKS (NPIX_F/512*4)   // 512

typedef unsigned long long u64;

// ---------------- scratch (device globals; no allocation allowed) ----------
__device__ __align__(16) float g_ru4[NPIX_F*4];   // 4 bilinear taps per down-pixel
__device__ unsigned char g_pseudo[NPIX_F];
__device__ float         g_sum_l[CC*DD];
__device__ float         g_sum_u[CC*DD];
__device__ float         g_cnt_l[CC];
__device__ float         g_wsum_u[CC];
__device__ float         g_cnt_u[CC];
__device__ float         g_mem[CC*DD];
__device__ int           g_init[CC];
__device__ double        g_ucps;
__device__ double        g_ce[4];
__device__ double        g_cv[4];
__device__ unsigned int  g_done;

__device__ __forceinline__ float warpSum(float v){
#pragma unroll
    for (int o = 16; o; o >>= 1) v += __shfl_down_sync(0xffffffffu, v, o);
    return v;
}
__device__ __forceinline__ void fma2(u64& d, u64 a, u64 b){
    asm("fma.rn.f32x2 %0, %1, %2, %0;" : "+l"(d) : "l"(a), "l"(b));
}
__device__ __forceinline__ float f2lo(u64 x){ return __uint_as_float((unsigned)(x & 0xffffffffu)); }
__device__ __forceinline__ float f2hi(u64 x){ return __uint_as_float((unsigned)(x >> 32)); }
__device__ __forceinline__ u64 fdup(float v){ unsigned u = __float_as_uint(v); return ((u64)u << 32) | u; }

// ---------------- kernel Z: zero scratch ------------------------------------
__global__ void kZ(){
    int t = threadIdx.x;
    for (int i = t; i < CC*DD; i += 256){ g_sum_l[i] = 0.f; g_sum_u[i] = 0.f; }
    if (t < CC){ g_cnt_l[t] = 0.f; g_wsum_u[t] = 0.f; g_cnt_u[t] = 0.f; }
    if (t == 0){ g_ucps = 0.0; g_done = 0u; }
    if (t < 4){ g_ce[t] = 0.0; g_cv[t] = 0.0; }
}

// ---------------- kernel A: per-pixel reliability + UCPS -------------------
__global__ __launch_bounds__(256) void kA(const float* __restrict__ L1,
                                          const float* __restrict__ L2){
    int idx = blockIdx.x * 256 + threadIdx.x;    // 0 .. NPIX_U-1
    int w = idx & (WW-1);
    int h = (idx >> 9) & (HH-1);
    int b = idx >> 18;
    size_t pix = (size_t)b * CC * HWU + (size_t)h * WW + w;

    float l1[CC], l2[CC], e1[CC], e2[CC];
#pragma unroll
    for (int c = 0; c < CC; c++){
        l1[c] = __ldg(&L1[pix + (size_t)c*HWU]);
        l2[c] = __ldg(&L2[pix + (size_t)c*HWU]);
    }
    float m1 = l1[0], m2 = l2[0];
    int y1 = 0, y2 = 0;
#pragma unroll
    for (int c = 1; c < CC; c++){
        if (l1[c] > m1){ m1 = l1[c]; y1 = c; }
        if (l2[c] > m2){ m2 = l2[c]; y2 = c; }
    }
    float s1 = 0.f, s2 = 0.f;
#pragma unroll
    for (int c = 0; c < CC; c++){
        e1[c] = __expf(l1[c] - m1); s1 += e1[c];
        e2[c] = __expf(l2[c] - m2); s2 += e2[c];
    }
    float lse1 = m1 + __logf(s1), lse2 = m2 + __logf(s2);
    float i1 = __fdividef(1.f, s1), i2 = __fdividef(1.f, s2);

    const float LOGEPS = -16.118095651f;         // log(1e-7)
    float kl = 0.f;
#pragma unroll
    for (int c = 0; c < CC; c++){
        float q1 = e1[c]*i1, q2 = e2[c]*i2;
        float logm = __logf(fmaxf(0.5f*(q1+q2), 1e-7f));
        kl += q1 * (fmaxf(l1[c]-lse1, LOGEPS) - logm)
            + q2 * (fmaxf(l2[c]-lse2, LOGEPS) - logm);
    }
    float conf = 0.5f*(i1 + i2);                 // max softmax = 1/s
    float r_u  = (y1 == y2) ? conf * __expf(-0.5f*kl) : 0.f;

    float l1y2 = 0.f, l2y1 = 0.f;
#pragma unroll
    for (int c = 0; c < CC; c++){
        if (c == y2) l1y2 = l1[c];
        if (c == y1) l2y1 = l2[c];
    }
    float contrib = r_u * ((lse1 - l1y2) + (lse2 - l2y1));

    // bilinear 4x downsample taps: pixels (4i+{1,2}, 4j+{1,2})
    int hm = h & 3, wm = w & 3;
    int dn = (b << 14) + ((h >> 2) << 7) + (w >> 2);
    if (((hm==1)||(hm==2)) && ((wm==1)||(wm==2)))
        g_ru4[dn*4 + (hm-1)*2 + (wm-1)] = r_u;   // plain store, all 4 slots written
    if (hm == 0 && wm == 0)
        g_pseudo[dn] = (unsigned char)((y1 == y2) ? y1 : 0);

    __shared__ float sred[8];
    float v = warpSum(contrib);
    if ((threadIdx.x & 31) == 0) sred[threadIdx.x >> 5] = v;
    __syncthreads();
    if (threadIdx.x == 0){
        float t = 0.f;
#pragma unroll
        for (int k = 0; k < 8; k++) t += sred[k];
        atomicAdd(&g_ucps, (double)t);
    }
}

// ------ kernel B: atomic-free segment sums via per-warp private accums -----
// block = 64 threads (2 warps); each warp serially handles 2 tiles of 32 px.
__global__ __launch_bounds__(64) void kB(const float* __restrict__ fl1,
                                         const float* __restrict__ fl2,
                                         const float* __restrict__ fu1,
                                         const float* __restrict__ fu2,
                                         const int*   __restrict__ gt,
                                         const int*   __restrict__ cur,
                                         const int*   __restrict__ mxit){
    __shared__ float s_priv[2][CC][DD];     // per-warp private labeled sums (19456 B)
    __shared__ float s_tile[2][64][33];     // per-warp staging, 64 d x 32 px (16896 B)
    __shared__ float s_u[CC*DD];            // block-shared anchored sums (9728 B)
    __shared__ float s_cl[CC], s_cu[CC], s_w[CC];
    __shared__ float s_tau;

    int tid = threadIdx.x, w = tid >> 5, lane = tid & 31;
    for (int i = tid; i < 2*CC*DD; i += 64) ((float*)s_priv)[i] = 0.f;
    for (int i = tid; i < CC*DD;   i += 64) s_u[i] = 0.f;
    if (tid < CC){ s_cl[tid]=0.f; s_cu[tid]=0.f; s_w[tid]=0.f; }
    if (tid == 0){
        int mi = *mxit; if (mi < 1) mi = 1;
        double ratio = (double)(*cur) / (double)mi;
        s_tau = (float)(0.85 - 0.35 * cos(1.5707963267948966 * ratio));
    }
    __syncthreads();

#pragma unroll 1
    for (int tt = 0; tt < 2; tt++){
        int tile = (blockIdx.x * 2 + w) * 2 + tt;   // 2048 tiles total
        int p0   = tile * 32;
        int b    = p0 >> 14;
        int ij0  = p0 & (HWF-1);

        int i  = (ij0 + lane) >> 7, j = (ij0 + lane) & 127;
        int lab_l = gt[(size_t)b*HWU + (size_t)(i*4)*WW + (j*4)];
        int lab_u = g_pseudo[p0 + lane];
        const float4* rp = (const float4*)&g_ru4[(p0 + lane)*4];
        float4 r4 = *rp;
        float r = 0.25f*(r4.x + r4.y + r4.z + r4.w);
        float wgt = (r > s_tau) ? r : 0.f;
        bool hot = (wgt != 0.f);

        atomicAdd(&s_cl[lab_l], 1.f);
        atomicAdd(&s_cu[lab_u], 1.f);
        if (hot) atomicAdd(&s_w[lab_u], wgt);

        size_t base = (size_t)b * DD * HWF + ij0;

#pragma unroll 1
        for (int half = 0; half < 2; half++){
            // stage 64 d-slices (coalesced)
#pragma unroll 8
            for (int dd = 0; dd < 64; dd++){
                size_t o = base + (size_t)(half*64 + dd) * HWF + lane;
                s_tile[w][dd][lane] = 0.5f*(__ldg(&fl1[o]) + __ldg(&fl2[o]));
            }
            __syncwarp();
            // accumulate: lane = d, two independent RMW chains
            float* privh = &s_priv[w][0][0] + half*64;
#pragma unroll 4
            for (int p = 0; p < 32; p++){
                int lab = __shfl_sync(0xffffffffu, lab_l, p);
                float v0 = s_tile[w][lane][p];
                float v1 = s_tile[w][32 + lane][p];
                float* pr = privh + lab*DD;
                pr[lane]      += v0;
                pr[32 + lane] += v1;
            }
            __syncwarp();
        }

        // rare anchored path for the unlabeled prototypes
        unsigned act = __ballot_sync(0xffffffffu, hot);
        while (act){
            int p = __ffs(act) - 1; act &= act - 1;
            int lab = __shfl_sync(0xffffffffu, lab_u, p);
            float wp = __shfl_sync(0xffffffffu, wgt, p);
#pragma unroll
            for (int k = 0; k < 4; k++){
                int d = k*32 + lane;
                size_t o = base + (size_t)d * HWF + p;
                float v = 0.5f*(__ldg(&fu1[o]) + __ldg(&fu2[o]));
                atomicAdd(&s_u[lab*DD + d], wp * v);
            }
        }
    }
    __syncthreads();

    // merge to global
    for (int t = tid; t < CC*DD; t += 64){
        float v = ((float*)s_priv)[t] + ((float*)s_priv)[CC*DD + t];
        atomicAdd(&g_sum_l[t], v);
        float u = s_u[t];
        if (u != 0.f) atomicAdd(&g_sum_u[t], u);
    }
    if (tid < CC){
        atomicAdd(&g_cnt_l [tid], s_cl[tid]);
        atomicAdd(&g_cnt_u [tid], s_cu[tid]);
        atomicAdd(&g_wsum_u[tid], s_w [tid]);
    }
}

// ---------------- kernel C: merge + memory update --------------------------
__global__ void kC(const float* __restrict__ memory,
                   const unsigned char* __restrict__ meminit){
    int c = blockIdx.x, d = threadIdx.x;         // 19 blocks x 128 threads
    __shared__ float swarp[4];

    float cntl = g_cnt_l[c], cntu = g_cnt_u[c], wsum = g_wsum_u[c];
    bool plp = (cntl >= 1.f), pup = (cntu >= 1.f);
    float pl = g_sum_l[c*DD + d] / (cntl + 1e-7f);
    float pu = g_sum_u[c*DD + d] / (wsum + 1e-7f);
    float merged = (plp && pup) ? (0.7f*pl + 0.3f*pu) : (plp ? pl : pu);

    float v = warpSum(merged * merged);
    if ((d & 31) == 0) swarp[d >> 5] = v;
    __syncthreads();
    float nrm = sqrtf(swarp[0] + swarp[1] + swarp[2] + swarp[3]);
    float pn = merged / fmaxf(nrm, 1e-12f);

    float mv = memory[c*DD + d];
    float ev = 0.999f*mv + 0.001f*pn;
    __syncthreads();
    float v2 = warpSum(ev * ev);
    if ((d & 31) == 0) swarp[d >> 5] = v2;
    __syncthreads();
    float n2 = sqrtf(swarp[0] + swarp[1] + swarp[2] + swarp[3]);
    float ema = ev / fmaxf(n2, 1e-12f);

    bool init = (meminit[c] != 0);
    bool present = plp || pup;
    g_mem[c*DD + d] = present ? (init ? ema : pn) : mv;
    if (d == 0) g_init[c] = (init || present) ? 1 : 0;
}

// ------ kernel D: hard contrastive (f32x2, 2 px/thread) + finalize ---------
__global__ __launch_bounds__(256) void kD(const float* __restrict__ fl1,
                                          const float* __restrict__ fl2,
                                          const float* __restrict__ fu1,
                                          const float* __restrict__ fu2,
                                          const int*   __restrict__ gt,
                                          float* __restrict__ out){
    int fid = blockIdx.y;
    const float* f = (fid==0) ? fl1 : (fid==1) ? fl2 : (fid==2) ? fu1 : fu2;

    __shared__ __align__(16) u64 sm2[DD*20];     // duplicated (m,m) pairs
    for (int t = threadIdx.x; t < DD*20; t += 256){
        int d = t / 20, c = t % 20;
        sm2[t] = fdup((c < CC) ? g_mem[c*DD + d] : 0.f);
    }
    __syncthreads();

    int n0 = (blockIdx.x * 256 + threadIdx.x) * 2;
    int b = n0 >> 14;
    size_t base = (size_t)b * DD * HWF + (n0 & (HWF-1));

    u64 acc[20];
#pragma unroll
    for (int c = 0; c < 20; c++) acc[c] = 0ull;
    u64 nrm2 = 0ull;
#pragma unroll 8
    for (int d = 0; d < DD; d++){
        u64 v2 = __ldg((const u64*)&f[base + (size_t)d * HWF]);
        fma2(nrm2, v2, v2);
        const ulonglong2* row = (const ulonglong2*)&sm2[d*20];
#pragma unroll
        for (int c2 = 0; c2 < 10; c2++){
            ulonglong2 rv = row[c2];
            fma2(acc[2*c2],   v2, rv.x);
            fma2(acc[2*c2+1], v2, rv.y);
        }
    }

    float blkce = 0.f, blkcv = 0.f;
#pragma unroll
    for (int half = 0; half < 2; half++){
        int n = n0 + half;
        float nrm = half ? f2hi(nrm2) : f2lo(nrm2);
        float inv = 5.0f / fmaxf(sqrtf(nrm), 1e-12f);   // 1/TAU_HARD = 5

        int lab;
        if (fid < 2){
            int j = n & 127, ii = (n >> 7) & 127;
            lab = gt[(size_t)b*HWU + (size_t)(ii*4)*WW + (j*4)];
        } else {
            lab = g_pseudo[n];
        }
        float valid = (float)g_init[lab];

        float mx = -1e30f, acclab = 0.f;
#pragma unroll
        for (int c = 0; c < CC; c++){
            float a = half ? f2hi(acc[c]) : f2lo(acc[c]);
            mx = fmaxf(mx, a);
            if (c == lab) acclab = a;
        }
        float s = 0.f;
#pragma unroll
        for (int c = 0; c < CC; c++){
            float a = half ? f2hi(acc[c]) : f2lo(acc[c]);
            s += __expf((a - mx) * inv);
        }
        float ce = mx*inv + __logf(s) - acclab*inv;
        blkce += ce * valid;
        blkcv += valid;
    }

    __shared__ float sA[8], sB[8];
    float a = warpSum(blkce);
    float bsum = warpSum(blkcv);
    if ((threadIdx.x & 31) == 0){ sA[threadIdx.x >> 5] = a; sB[threadIdx.x >> 5] = bsum; }
    __syncthreads();
    if (threadIdx.x == 0){
        float ta = 0.f, tb = 0.f;
#pragma unroll
        for (int k = 0; k < 8; k++){ ta += sA[k]; tb += sB[k]; }
        atomicAdd(&g_ce[fid], (double)ta);
        atomicAdd(&g_cv[fid], (double)tb);
        __threadfence();
        unsigned done = atomicAdd(&g_done, 1u);
        if (done == KD_BLOCKS - 1){
            double h[4];
#pragma unroll
            for (int i = 0; i < 4; i++){
                double nv = g_cv[i];
                h[i] = (nv > 0.0) ? g_ce[i] / fmax(nv, 1.0) : 0.0;
            }
            out[0] = (float)(0.5*(h[0] + h[1]) + 0.5*(h[2] + h[3]));
            out[1] = (float)(g_ucps / (double)NPIX_U);
        }
    }
}

// ---------------- launcher ---------------------------------------------------
extern "C" void kernel_launch(void* const* d_in, const int* in_sizes, int n_in,
                              void* d_out, int out_size){
    const float* fl1 = (const float*)d_in[0];
    const float* fl2 = (const float*)d_in[1];
    const float* fu1 = (const float*)d_in[2];
    const float* fu2 = (const float*)d_in[3];
    // d_in[4], d_in[5] (logits_l1/l2) unused by the reference
    const float* lu1 = (const float*)d_in[6];
    const float* lu2 = (const float*)d_in[7];
    const float* mem = (const float*)d_in[8];
    const int*   gt  = (const int*)d_in[9];
    const unsigned char* meminit = (const unsigned char*)d_in[10];
    const int*   cur = (const int*)d_in[11];
    const int*   mx  = (const int*)d_in[12];

    kZ<<<1, 256>>>();
    kA<<<NPIX_U/256, 256>>>(lu1, lu2);
    kB<<<512, 64>>>(fl1, fl2, fu1, fu2, gt, cur, mx);
    kC<<<CC, DD>>>(mem, meminit);
    kD<<<dim3(NPIX_F/512, 4), 256>>>(fl1, fl2, fu1, fu2, gt, (float*)d_out);
}